// round 14
// baseline (speedup 1.0000x reference)
#include <cuda_runtime.h>
#include <math.h>

#define BN 2
#define KC 12
#define HH 120
#define WW 160
#define HW (HH*WW)          // 19200
#define NB 100
#define DD 128
#define NVOX (DD*DD*DD)
#define NVOXB (BN*NVOX)     // 4194304
#define NW 4                // 32-bit words per x-row
#define ROWW (NW*DD)        // word stride per z-slice = 512
#define NWORDS (NVOXB/32)   // 131072
#define WPB 65536           // words per batch
#define FEAT_ELEMS (BN*15*NB*HW)
#define FK_OFF FEAT_ELEMS
#define MASK_OFF (FEAT_ELEMS + NVOXB)

// voxel work appended to k_feat grid: z slices [30, 30+VZ); 4 voxels per thread
#define VZ 22               // 22*150 blocks * 320 thr * 4 vox = 4,224,000 >= NVOXB

// ---------------- scratch (device globals; no allocations) ----------------
__device__ float          g_sm[BN*KC*HW];   // softmax features
__device__ int            g_di[BN*HW];      // depth_index
__device__ unsigned int   g_dp[BN*HW];      // packed: di | (dmb<<16)
__device__ unsigned char  g_sind[BN*HW];    // sem>=10 indicator
__device__ float          g_sd[BN*HW];      // clamped depth
__device__ float          g_sx[BN*WW];
__device__ float          g_sy[BN*HH];
__device__ unsigned int   g_pf[NWORDS];     // packed feat_kept
__device__ unsigned int   g_pk[NWORDS];     // packed kept
__device__ unsigned int   g_pa[NWORDS];     // packed padding_kept
__device__ unsigned int   g_pb[NWORDS];     // packed union
__device__ int            g_bp[BN];

// ---------------- stage 1: per-pixel softmax/argmax/depth (chip-wide) ----------------
__global__ void k_pix(const float* __restrict__ sem, const float* __restrict__ depth){
    int i = blockIdx.x*blockDim.x + threadIdx.x;
    if (i == 0){ g_bp[0] = 0; g_bp[1] = 0; }
    if (i >= BN*HW) return;
    int b = i / HW, p = i - b*HW;
    const float* s = sem + (size_t)b*KC*HW + p;
    float v[KC]; float mx = -1e30f; int am = 0;
    #pragma unroll
    for (int k = 0; k < KC; k++){ v[k] = s[(size_t)k*HW]; if (v[k] > mx){ mx = v[k]; am = k; } }
    float sum = 0.f;
    #pragma unroll
    for (int k = 0; k < KC; k++){ v[k] = expf(v[k]-mx); sum += v[k]; }
    float inv = 1.f/sum;
    float* o = g_sm + (size_t)b*KC*HW + p;
    #pragma unroll
    for (int k = 0; k < KC; k++) o[(size_t)k*HW] = v[k]*inv;
    g_sind[i] = (unsigned char)(am >= 10);
    float dc = fminf(depth[i], 6.f);
    g_di[i] = (int)(dc/6.f*100.f);
    g_sd[i] = dc;
}

// ---------------- stage 2: erosion + axis maxes + find_none + pack (smem, 2 blocks) ----------------
__device__ void find_none_dev(const float* a, int n, float* out){
    float suf[WW];
    float run = INFINITY;
    for (int ii = n-1; ii >= 0; ii--){
        suf[ii] = run;
        float av = (a[ii] != 0.f) ? a[ii] : INFINITY;
        run = fminf(run, av);
    }
    float m = INFINITY;
    for (int ii = 0; ii < n; ii++){
        float l = isinf(m)      ? 0.f : m;
        float r = isinf(suf[ii])? 0.f : suf[ii];
        float val = (a[ii] == 0.f) ? fmaxf(l, r) : a[ii];
        if (val != 0.f) m = fminf(m, val);
        out[ii] = val;
    }
}

#define SM2_BYTES (HW*4 + HW + HW + (HH+WW+WW+HH)*4 + 16)

__global__ void k_small(){
    extern __shared__ unsigned char smraw[];
    float*         s_sd = (float*)smraw;
    unsigned char* s_si = (unsigned char*)(s_sd + HW);
    unsigned char* s_rm = s_si + HW;
    float* ymax = (float*)(s_rm + HW);
    float* xmax = ymax + HH;
    float* colm = xmax + WW;
    float* rowm = colm + WW;
    float* vv   = rowm + HH;

    int b = blockIdx.x, tid = threadIdx.x, nt = blockDim.x;

    for (int p = tid; p < HW; p += nt) s_si[p] = g_sind[b*HW + p];
    __syncthreads();
    for (int p = tid; p < HW; p += nt){
        int h = p / WW, w = p - h*WW;
        unsigned char m = 1;
        #pragma unroll
        for (int dw = -2; dw <= 2; dw++){
            int w2 = w + dw;
            if (w2 >= 0 && w2 < WW) m &= s_si[h*WW + w2];
        }
        s_rm[p] = m;
    }
    __syncthreads();
    for (int p = tid; p < HW; p += nt){
        int h = p / WW;
        unsigned char m = 1;
        #pragma unroll
        for (int dh = -2; dh <= 2; dh++){
            int h2 = h + dh;
            if (h2 >= 0 && h2 < HH) m &= s_rm[h2*WW + (p - h*WW)];
        }
        s_sd[p] = m ? g_sd[b*HW + p] : 0.f;
    }
    __syncthreads();

    for (int h = tid; h < HH; h += nt){
        float m = 0.f; for (int w = 0; w < WW; w++) m = fmaxf(m, s_sd[h*WW+w]); ymax[h] = m;
    }
    for (int w = tid; w < WW; w += nt){
        float m = 0.f; for (int h = 0; h < HH; h++) m = fmaxf(m, s_sd[h*WW+w]); xmax[w] = m;
    }
    __syncthreads();
    if (tid == 0){
        float a = 0.f; for (int h = 0; h < HH; h++)      if (ymax[h] != 0.f){ a = ymax[h]; break; } vv[0] = a;
        a = 0.f;       for (int h = HH-1; h >= 0; h--)   if (ymax[h] != 0.f){ a = ymax[h]; break; } vv[1] = a;
        a = 0.f;       for (int w = 0; w < WW; w++)      if (xmax[w] != 0.f){ a = xmax[w]; break; } vv[2] = a;
        a = 0.f;       for (int w = WW-1; w >= 0; w--)   if (xmax[w] != 0.f){ a = xmax[w]; break; } vv[3] = a;
    }
    __syncthreads();
    float vy = vv[0], vyr = vv[1], vx = vv[2], vxr = vv[3];
    auto sdval = [&](int h, int w) -> float {
        float v = s_sd[h*WW + w];
        if (w == 0)      return (v != 0.f) ? v : vx;
        if (w == WW-1)   return (v != 0.f) ? v : vxr;
        if (h == 0)      return (v != 0.f) ? v : vy;
        if (h == HH-1)   return (v != 0.f) ? v : vyr;
        return v;
    };
    for (int w = tid; w < WW; w += nt){
        float m = 0.f; for (int h = 0; h < HH; h++) m = fmaxf(m, sdval(h, w)); colm[w] = m;
    }
    for (int h = tid; h < HH; h += nt){
        float m = 0.f; for (int w = 0; w < WW; w++) m = fmaxf(m, sdval(h, w)); rowm[h] = m;
    }
    __syncthreads();
    // find_none results also land in smem (xmax/ymax reused) for the pack phase
    if (tid == 0){  find_none_dev(colm, WW, xmax); for (int w = 0; w < WW; w++) g_sx[b*WW+w] = xmax[w]; }
    if (tid == 32){ find_none_dev(rowm, HH, ymax); for (int h = 0; h < HH; h++) g_sy[b*HH+h] = ymax[h]; }
    __syncthreads();
    // pack phase: g_dp[p] = di | (dmb << 16)
    for (int p = tid; p < HW; p += nt){
        int h = p / WW, w = p - h*WW;
        unsigned dmb = (unsigned)(int)(fminf(xmax[w], ymax[h])/6.f*100.f);
        g_dp[b*HW + p] = (unsigned)g_di[b*HW + p] | (dmb << 16);
    }
}

// ---------------- stage 3: fused features + voxel gather (x4 vectorized) ----------------
__global__ void __launch_bounds__(320, 6)
k_feat(const float* __restrict__ occ,
       const float4* __restrict__ mapping,
       const uint4* __restrict__ kept4,
       float* __restrict__ out){
    if (blockIdx.z >= 30){
        // ---- voxel path: 4 voxels per thread, ONE packed gather per kept voxel ----
        int lb  = (blockIdx.z - 30)*150 + blockIdx.y*30 + blockIdx.x;
        int tid = threadIdx.y*160 + threadIdx.x;
        int q   = lb*320 + tid;                 // quad index
        if (q >= NVOXB/4) return;               // boundary retires whole warps
        uint4 kw = __ldcs(&kept4[q]);
        unsigned fnib = 0, knib = 0;
        float f[4];
        #pragma unroll
        for (int k = 0; k < 4; k++){
            unsigned kv = (&kw.x)[k];
            bool fk = false;
            if (kv){
                float4 m = __ldcs(&mapping[q*4 + k]);
                int b = (int)m.x, x = (int)m.y, y = (int)m.z;
                int didx = (int)(m.w*100.f/6.f);
                unsigned pw = g_dp[b*HW + y*WW + x];
                int di  = (int)(pw & 0xFFFFu);
                int dmb = (int)(pw >> 16);
                fk = (didx > di - 3) && (didx < dmb + 5);
            }
            f[k] = fk ? 1.f : 0.f;
            fnib |= (fk ? 1u : 0u) << k;
            knib |= (kv ? 1u : 0u) << k;
        }
        unsigned sh = 4*(tid & 7);
        unsigned fw = fnib << sh, kwp = knib << sh;
        #pragma unroll
        for (int off = 1; off < 8; off <<= 1){
            fw  |= __shfl_xor_sync(0xffffffffu, fw,  off);
            kwp |= __shfl_xor_sync(0xffffffffu, kwp, off);
        }
        if ((tid & 7) == 0){
            g_pf[q >> 3] = fw;
            g_pk[q >> 3] = kwp;
        }
        __stcs(&((float4*)out)[FK_OFF/4 + q], make_float4(f[0], f[1], f[2], f[3]));
        return;
    }
    // ---- feature path ----
    int p4 = blockIdx.x*160 + threadIdx.x;           // 0..4799
    int d0 = blockIdx.y*20 + threadIdx.y*10;         // 0..90 step 10
    int cz = blockIdx.z; int b = cz/15, c = cz - b*15;
    float4* ob = (float4*)out + (size_t)cz*NB*(HW/4) + p4;
    if (c < KC){
        float4 o = ((const float4*)g_sm)[(size_t)(b*KC + c)*(HW/4) + p4];
        #pragma unroll
        for (int q = 0; q < 10; q++)
            __stcs(&ob[(size_t)(d0+q)*(HW/4)], o);
    } else if (c == 13){
        const int4 di4 = ((const int4*)g_di)[b*(HW/4) + p4];
        #pragma unroll
        for (int q = 0; q < 10; q++){
            int d = d0 + q;
            float4 o;
            o.x = (d > di4.x) ? 1.f : ((d < di4.x) ? -1.f : 0.f);
            o.y = (d > di4.y) ? 1.f : ((d < di4.y) ? -1.f : 0.f);
            o.z = (d > di4.z) ? 1.f : ((d < di4.z) ? -1.f : 0.f);
            o.w = (d > di4.w) ? 1.f : ((d < di4.w) ? -1.f : 0.f);
            __stcs(&ob[(size_t)d*(HW/4)], o);
        }
    } else if (c == 14){
        const int4 di4 = ((const int4*)g_di)[b*(HW/4) + p4];
        #pragma unroll
        for (int q = 0; q < 10; q++){
            int d = d0 + q;
            float4 o;
            o.x = fabsf((float)(d - di4.x)*0.06f);
            o.y = fabsf((float)(d - di4.y)*0.06f);
            o.z = fabsf((float)(d - di4.z)*0.06f);
            o.w = fabsf((float)(d - di4.w)*0.06f);
            __stcs(&ob[(size_t)d*(HW/4)], o);
        }
    } else { // c == 12 : depth_weight — packed di/dmb table
        const uint4 dp4 = ((const uint4*)g_dp)[b*(HW/4) + p4];
        int di[4], dmb[4];
        #pragma unroll
        for (int l = 0; l < 4; l++){
            unsigned pw = (&dp4.x)[l];
            di[l]  = (int)(pw & 0xFFFFu);
            dmb[l] = (int)(pw >> 16);
        }
        const float4* occ4 = (const float4*)occ + (size_t)b*NB*(HW/4) + p4;
        #pragma unroll
        for (int q = 0; q < 10; q++){
            int d = d0 + q;
            float4 ov = __ldcs(&occ4[(size_t)d*(HW/4)]);
            float ovv[4] = {ov.x, ov.y, ov.z, ov.w};
            float res[4];
            #pragma unroll
            for (int l = 0; l < 4; l++){
                bool kp = (d > di[l] - 3) && (d < dmb[l] + 5);
                res[l] = kp ? (1.f/(1.f + expf(-ovv[l]))) : 0.f;
            }
            __stcs(&ob[(size_t)d*(HW/4)], make_float4(res[0], res[1], res[2], res[3]));
        }
    }
}

// ---------------- packed 5^3 dilation (single-lane, plain loads) ----------------
template <typename F>
__device__ __forceinline__ unsigned dil3d_f(F load, int i){
    int t = i >> 2;
    int y = t & (DD-1);
    int z = (t >> 7) & (DD-1);
    unsigned zy = 0;
    #pragma unroll
    for (int dz = -2; dz <= 2; dz++){
        int zz = z + dz; if (zz < 0 || zz >= DD) continue;
        #pragma unroll
        for (int dy = -2; dy <= 2; dy++){
            int yy = y + dy; if (yy < 0 || yy >= DD) continue;
            zy |= load(i + (dz*DD + dy)*NW);
        }
    }
    int wx = i & (NW-1);
    unsigned p = __shfl_up_sync(0xffffffffu, zy, 1);
    unsigned n = __shfl_down_sync(0xffffffffu, zy, 1);
    if (wx == 0)    p = 0u;
    if (wx == NW-1) n = 0u;
    return zy | (zy<<1) | (zy<<2) | (zy>>1) | (zy>>2)
              | (p>>31) | (p>>30) | (n<<31) | (n<<30);
}

// padding_kept = dil3d(feat_kept) & kept; popcount -> g_bp; &= ~feat_kept
__global__ void k_dpk(){
    __shared__ int sc;
    int i = blockIdx.x*256 + threadIdx.x;
    if (threadIdx.x == 0) sc = 0;
    __syncthreads();
    unsigned a = dil3d_f([](int j){ return g_pf[j]; }, i) & g_pk[i];
    int cnt = __popc(a);
    #pragma unroll
    for (int off = 16; off > 0; off >>= 1) cnt += __shfl_down_sync(0xffffffffu, cnt, off);
    if ((threadIdx.x & 31) == 0 && cnt) atomicAdd(&sc, cnt);
    g_pa[i] = a & ~g_pf[i];
    __syncthreads();
    if (threadIdx.x == 0 && sc) atomicAdd(&g_bp[i >> 16], sc);
}

// materialize union = feat_kept | padding_even (virtual fix bit); 5 loads/word
__global__ void k_unionw(){
    int i = blockIdx.x*256 + threadIdx.x;
    int t = i >> 2;
    int y = t & (DD-1);
    int z = (t >> 7) & (DD-1);
    int b = i >> 16;
    unsigned pe = 0;
    if (!(y & 1) && !(z & 1)){
        int fixw = (g_bp[b] == 0) ? (b*WPB + 127*ROWW + 127*NW + 3) : -1;
        auto L = [&](int j) -> unsigned {
            unsigned v = g_pa[j];
            if (j == fixw) v |= 0x80000000u;
            return v;
        };
        unsigned q = L(i) | L(i+NW) | L(i+ROWW) | L(i+ROWW+NW);
        pe = (q | (q >> 1)) & 0x55555555u;
    }
    g_pb[i] = g_pf[i] | pe;
}

// mask = dil3d(union) with plain loads, unpacked to floats
__global__ void k_dmask(float* __restrict__ out){
    int i = blockIdx.x*256 + threadIdx.x;
    unsigned r = dil3d_f([](int j){ return g_pb[j]; }, i);
    float4* o = (float4*)(out + MASK_OFF + (size_t)i*32);
    #pragma unroll
    for (int j = 0; j < 8; j++){
        __stcs(&o[j], make_float4((r>>(4*j))&1 ? 1.f:0.f, (r>>(4*j+1))&1 ? 1.f:0.f,
                                  (r>>(4*j+2))&1 ? 1.f:0.f, (r>>(4*j+3))&1 ? 1.f:0.f));
    }
}

// ---------------- launch ----------------
extern "C" void kernel_launch(void* const* d_in, const int* in_sizes, int n_in,
                              void* d_out, int out_size){
    const float* sem   = (const float*)d_in[0];
    const float* depth = (const float*)d_in[1];
    const float* occ   = (const float*)d_in[2];
    const uint4* kept4 = (const uint4*)d_in[3];
    const float4* mapping = (const float4*)d_in[4];
    float* out = (float*)d_out;

    cudaFuncSetAttribute(k_small, cudaFuncAttributeMaxDynamicSharedMemorySize, SM2_BYTES);

    const int T = 256;
    const int WG = NWORDS/256;  // 512
    k_pix   <<<(BN*HW + T-1)/T, T>>>(sem, depth);
    k_small <<<BN, 512, SM2_BYTES>>>();
    k_feat  <<<dim3(30, 5, 30 + VZ), dim3(160, 2)>>>(occ, mapping, kept4, out);
    k_dpk   <<<WG, T>>>();
    k_unionw<<<WG, T>>>();
    k_dmask <<<WG, T>>>(out);
}

// round 15
// speedup vs baseline: 1.1211x; 1.1211x over previous
#include <cuda_runtime.h>
#include <math.h>

#define BN 2
#define KC 12
#define HH 120
#define WW 160
#define HW (HH*WW)          // 19200
#define NB 100
#define DD 128
#define NVOX (DD*DD*DD)
#define NVOXB (BN*NVOX)     // 4194304
#define NW 4                // 32-bit words per x-row
#define ROWW (NW*DD)        // word stride per z-slice = 512
#define NWORDS (NVOXB/32)   // 131072
#define WPB 65536           // words per batch
#define FEAT_ELEMS (BN*15*NB*HW)
#define FK_OFF FEAT_ELEMS
#define MASK_OFF (FEAT_ELEMS + NVOXB)

// voxel work appended to k_feat grid: z slices [30, 30+VZ); 4 voxels per thread
#define VZ 22               // 22*150 blocks * 320 thr * 4 vox = 4,224,000 >= NVOXB

// ---------------- scratch (device globals; no allocations) ----------------
__device__ float          g_sm[BN*KC*HW];   // softmax features
__device__ int            g_di[BN*HW];      // depth_index
__device__ unsigned char  g_sind[BN*HW];    // sem>=10 indicator
__device__ float          g_sd[BN*HW];      // clamped depth
__device__ float          g_sx[BN*WW];
__device__ float          g_sy[BN*HH];
__device__ unsigned int   g_pf[NWORDS];     // packed feat_kept
__device__ unsigned int   g_pk[NWORDS];     // packed kept
__device__ unsigned int   g_pa[NWORDS];     // packed padding_kept
__device__ unsigned int   g_pb[NWORDS];     // packed union
__device__ int            g_bp[BN];

// ---------------- stage 1: per-pixel softmax/argmax/depth (chip-wide) ----------------
__global__ void k_pix(const float* __restrict__ sem, const float* __restrict__ depth){
    int i = blockIdx.x*blockDim.x + threadIdx.x;
    if (i == 0){ g_bp[0] = 0; g_bp[1] = 0; }
    if (i >= BN*HW) return;
    int b = i / HW, p = i - b*HW;
    const float* s = sem + (size_t)b*KC*HW + p;
    float v[KC]; float mx = -1e30f; int am = 0;
    #pragma unroll
    for (int k = 0; k < KC; k++){ v[k] = s[(size_t)k*HW]; if (v[k] > mx){ mx = v[k]; am = k; } }
    float sum = 0.f;
    #pragma unroll
    for (int k = 0; k < KC; k++){ v[k] = expf(v[k]-mx); sum += v[k]; }
    float inv = 1.f/sum;
    float* o = g_sm + (size_t)b*KC*HW + p;
    #pragma unroll
    for (int k = 0; k < KC; k++) o[(size_t)k*HW] = v[k]*inv;
    g_sind[i] = (unsigned char)(am >= 10);
    float dc = fminf(depth[i], 6.f);
    g_di[i] = (int)(dc/6.f*100.f);
    g_sd[i] = dc;
}

// ---------------- stage 2: fused erosion + axis maxes + find_none (smem, 2 blocks) ----------------
__device__ void find_none_dev(const float* a, int n, float* out){
    float suf[WW];
    float run = INFINITY;
    for (int ii = n-1; ii >= 0; ii--){
        suf[ii] = run;
        float av = (a[ii] != 0.f) ? a[ii] : INFINITY;
        run = fminf(run, av);
    }
    float m = INFINITY;
    for (int ii = 0; ii < n; ii++){
        float l = isinf(m)      ? 0.f : m;
        float r = isinf(suf[ii])? 0.f : suf[ii];
        float val = (a[ii] == 0.f) ? fmaxf(l, r) : a[ii];
        if (val != 0.f) m = fminf(m, val);
        out[ii] = val;
    }
}

#define SM2_BYTES (HW*4 + HW + HW + (HH+WW+WW+HH)*4 + 16)

__global__ void k_small(){
    extern __shared__ unsigned char smraw[];
    float*         s_sd = (float*)smraw;
    unsigned char* s_si = (unsigned char*)(s_sd + HW);
    unsigned char* s_rm = s_si + HW;
    float* ymax = (float*)(s_rm + HW);
    float* xmax = ymax + HH;
    float* colm = xmax + WW;
    float* rowm = colm + WW;
    float* vv   = rowm + HH;

    int b = blockIdx.x, tid = threadIdx.x, nt = blockDim.x;

    for (int p = tid; p < HW; p += nt) s_si[p] = g_sind[b*HW + p];
    __syncthreads();
    for (int p = tid; p < HW; p += nt){
        int h = p / WW, w = p - h*WW;
        unsigned char m = 1;
        #pragma unroll
        for (int dw = -2; dw <= 2; dw++){
            int w2 = w + dw;
            if (w2 >= 0 && w2 < WW) m &= s_si[h*WW + w2];
        }
        s_rm[p] = m;
    }
    __syncthreads();
    for (int p = tid; p < HW; p += nt){
        int h = p / WW;
        unsigned char m = 1;
        #pragma unroll
        for (int dh = -2; dh <= 2; dh++){
            int h2 = h + dh;
            if (h2 >= 0 && h2 < HH) m &= s_rm[h2*WW + (p - h*WW)];
        }
        s_sd[p] = m ? g_sd[b*HW + p] : 0.f;
    }
    __syncthreads();

    for (int h = tid; h < HH; h += nt){
        float m = 0.f; for (int w = 0; w < WW; w++) m = fmaxf(m, s_sd[h*WW+w]); ymax[h] = m;
    }
    for (int w = tid; w < WW; w += nt){
        float m = 0.f; for (int h = 0; h < HH; h++) m = fmaxf(m, s_sd[h*WW+w]); xmax[w] = m;
    }
    __syncthreads();
    if (tid == 0){
        float a = 0.f; for (int h = 0; h < HH; h++)      if (ymax[h] != 0.f){ a = ymax[h]; break; } vv[0] = a;
        a = 0.f;       for (int h = HH-1; h >= 0; h--)   if (ymax[h] != 0.f){ a = ymax[h]; break; } vv[1] = a;
        a = 0.f;       for (int w = 0; w < WW; w++)      if (xmax[w] != 0.f){ a = xmax[w]; break; } vv[2] = a;
        a = 0.f;       for (int w = WW-1; w >= 0; w--)   if (xmax[w] != 0.f){ a = xmax[w]; break; } vv[3] = a;
    }
    __syncthreads();
    float vy = vv[0], vyr = vv[1], vx = vv[2], vxr = vv[3];
    auto sdval = [&](int h, int w) -> float {
        float v = s_sd[h*WW + w];
        if (w == 0)      return (v != 0.f) ? v : vx;
        if (w == WW-1)   return (v != 0.f) ? v : vxr;
        if (h == 0)      return (v != 0.f) ? v : vy;
        if (h == HH-1)   return (v != 0.f) ? v : vyr;
        return v;
    };
    for (int w = tid; w < WW; w += nt){
        float m = 0.f; for (int h = 0; h < HH; h++) m = fmaxf(m, sdval(h, w)); colm[w] = m;
    }
    for (int h = tid; h < HH; h += nt){
        float m = 0.f; for (int w = 0; w < WW; w++) m = fmaxf(m, sdval(h, w)); rowm[h] = m;
    }
    __syncthreads();
    if (tid == 0)  find_none_dev(colm, WW, g_sx + b*WW);
    if (tid == 32) find_none_dev(rowm, HH, g_sy + b*HH);
}

// ---------------- stage 3: fused features + voxel gather (x4 vectorized) ----------------
__global__ void __launch_bounds__(320, 6)
k_feat(const float* __restrict__ occ,
       const float4* __restrict__ mapping,
       const uint4* __restrict__ kept4,
       float* __restrict__ out){
    if (blockIdx.z >= 30){
        // ---- voxel path: 4 voxels per thread ----
        int lb  = (blockIdx.z - 30)*150 + blockIdx.y*30 + blockIdx.x;
        int tid = threadIdx.y*160 + threadIdx.x;
        int q   = lb*320 + tid;                 // quad index
        if (q >= NVOXB/4) return;               // boundary retires whole warps
        uint4 kw = __ldcs(&kept4[q]);
        unsigned fnib = 0, knib = 0;
        float f[4];
        #pragma unroll
        for (int k = 0; k < 4; k++){
            unsigned kv = (&kw.x)[k];
            bool fk = false;
            if (kv){
                float4 m = __ldcs(&mapping[q*4 + k]);
                int b = (int)m.x, x = (int)m.y, y = (int)m.z;
                int didx = (int)(m.w*100.f/6.f);
                int di  = g_di[b*HW + y*WW + x];
                int dmb = (int)(fminf(g_sx[b*WW + x], g_sy[b*HH + y])/6.f*100.f);
                fk = (didx > di - 3) && (didx < dmb + 5);
            }
            f[k] = fk ? 1.f : 0.f;
            fnib |= (fk ? 1u : 0u) << k;
            knib |= (kv ? 1u : 0u) << k;
        }
        unsigned sh = 4*(tid & 7);
        unsigned fw = fnib << sh, kwp = knib << sh;
        #pragma unroll
        for (int off = 1; off < 8; off <<= 1){
            fw  |= __shfl_xor_sync(0xffffffffu, fw,  off);
            kwp |= __shfl_xor_sync(0xffffffffu, kwp, off);
        }
        if ((tid & 7) == 0){
            g_pf[q >> 3] = fw;
            g_pk[q >> 3] = kwp;
        }
        __stcs(&((float4*)out)[FK_OFF/4 + q], make_float4(f[0], f[1], f[2], f[3]));
        return;
    }
    // ---- feature path ----
    int p4 = blockIdx.x*160 + threadIdx.x;           // 0..4799
    int d0 = blockIdx.y*20 + threadIdx.y*10;         // 0..90 step 10
    int cz = blockIdx.z; int b = cz/15, c = cz - b*15;
    float4* ob = (float4*)out + (size_t)cz*NB*(HW/4) + p4;
    if (c < KC){
        float4 o = ((const float4*)g_sm)[(size_t)(b*KC + c)*(HW/4) + p4];
        #pragma unroll
        for (int q = 0; q < 10; q++)
            __stcs(&ob[(size_t)(d0+q)*(HW/4)], o);
    } else if (c == 13){
        const int4 di4 = ((const int4*)g_di)[b*(HW/4) + p4];
        #pragma unroll
        for (int q = 0; q < 10; q++){
            int d = d0 + q;
            float4 o;
            o.x = (d > di4.x) ? 1.f : ((d < di4.x) ? -1.f : 0.f);
            o.y = (d > di4.y) ? 1.f : ((d < di4.y) ? -1.f : 0.f);
            o.z = (d > di4.z) ? 1.f : ((d < di4.z) ? -1.f : 0.f);
            o.w = (d > di4.w) ? 1.f : ((d < di4.w) ? -1.f : 0.f);
            __stcs(&ob[(size_t)d*(HW/4)], o);
        }
    } else if (c == 14){
        const int4 di4 = ((const int4*)g_di)[b*(HW/4) + p4];
        #pragma unroll
        for (int q = 0; q < 10; q++){
            int d = d0 + q;
            float4 o;
            o.x = fabsf((float)(d - di4.x)*0.06f);
            o.y = fabsf((float)(d - di4.y)*0.06f);
            o.z = fabsf((float)(d - di4.z)*0.06f);
            o.w = fabsf((float)(d - di4.w)*0.06f);
            __stcs(&ob[(size_t)d*(HW/4)], o);
        }
    } else { // c == 12 : depth_weight
        int h = p4/40, w0 = (p4 - h*40)*4;
        float sy = g_sy[b*HH + h];
        const int4 di4 = ((const int4*)g_di)[b*(HW/4) + p4];
        int di[4] = {di4.x, di4.y, di4.z, di4.w};
        int dmb[4];
        #pragma unroll
        for (int l = 0; l < 4; l++)
            dmb[l] = (int)(fminf(g_sx[b*WW + w0 + l], sy)/6.f*100.f);
        const float4* occ4 = (const float4*)occ + (size_t)b*NB*(HW/4) + p4;
        #pragma unroll
        for (int q = 0; q < 10; q++){
            int d = d0 + q;
            float4 ov = __ldcs(&occ4[(size_t)d*(HW/4)]);
            float ovv[4] = {ov.x, ov.y, ov.z, ov.w};
            float res[4];
            #pragma unroll
            for (int l = 0; l < 4; l++){
                bool kp = (d > di[l] - 3) && (d < dmb[l] + 5);
                res[l] = kp ? (1.f/(1.f + expf(-ovv[l]))) : 0.f;
            }
            __stcs(&ob[(size_t)d*(HW/4)], make_float4(res[0], res[1], res[2], res[3]));
        }
    }
}

// ---------------- packed 5^3 dilation (single-lane, plain loads) ----------------
template <typename F>
__device__ __forceinline__ unsigned dil3d_f(F load, int i){
    int t = i >> 2;
    int y = t & (DD-1);
    int z = (t >> 7) & (DD-1);
    unsigned zy = 0;
    #pragma unroll
    for (int dz = -2; dz <= 2; dz++){
        int zz = z + dz; if (zz < 0 || zz >= DD) continue;
        #pragma unroll
        for (int dy = -2; dy <= 2; dy++){
            int yy = y + dy; if (yy < 0 || yy >= DD) continue;
            zy |= load(i + (dz*DD + dy)*NW);
        }
    }
    int wx = i & (NW-1);
    unsigned p = __shfl_up_sync(0xffffffffu, zy, 1);
    unsigned n = __shfl_down_sync(0xffffffffu, zy, 1);
    if (wx == 0)    p = 0u;
    if (wx == NW-1) n = 0u;
    return zy | (zy<<1) | (zy<<2) | (zy>>1) | (zy>>2)
              | (p>>31) | (p>>30) | (n<<31) | (n<<30);
}

// padding_kept = dil3d(feat_kept) & kept; popcount -> g_bp; &= ~feat_kept
__global__ void k_dpk(){
    __shared__ int sc;
    int i = blockIdx.x*256 + threadIdx.x;
    if (threadIdx.x == 0) sc = 0;
    __syncthreads();
    unsigned a = dil3d_f([](int j){ return g_pf[j]; }, i) & g_pk[i];
    int cnt = __popc(a);
    #pragma unroll
    for (int off = 16; off > 0; off >>= 1) cnt += __shfl_down_sync(0xffffffffu, cnt, off);
    if ((threadIdx.x & 31) == 0 && cnt) atomicAdd(&sc, cnt);
    g_pa[i] = a & ~g_pf[i];
    __syncthreads();
    if (threadIdx.x == 0 && sc) atomicAdd(&g_bp[i >> 16], sc);
}

// materialize union = feat_kept | padding_even (virtual fix bit); 5 loads/word
__global__ void k_unionw(){
    int i = blockIdx.x*256 + threadIdx.x;
    int t = i >> 2;
    int y = t & (DD-1);
    int z = (t >> 7) & (DD-1);
    int b = i >> 16;
    unsigned pe = 0;
    if (!(y & 1) && !(z & 1)){
        int fixw = (g_bp[b] == 0) ? (b*WPB + 127*ROWW + 127*NW + 3) : -1;
        auto L = [&](int j) -> unsigned {
            unsigned v = g_pa[j];
            if (j == fixw) v |= 0x80000000u;
            return v;
        };
        unsigned q = L(i) | L(i+NW) | L(i+ROWW) | L(i+ROWW+NW);
        pe = (q | (q >> 1)) & 0x55555555u;
    }
    g_pb[i] = g_pf[i] | pe;
}

// mask = dil3d(union) with plain loads, unpacked to floats
__global__ void k_dmask(float* __restrict__ out){
    int i = blockIdx.x*256 + threadIdx.x;
    unsigned r = dil3d_f([](int j){ return g_pb[j]; }, i);
    float4* o = (float4*)(out + MASK_OFF + (size_t)i*32);
    #pragma unroll
    for (int j = 0; j < 8; j++){
        __stcs(&o[j], make_float4((r>>(4*j))&1 ? 1.f:0.f, (r>>(4*j+1))&1 ? 1.f:0.f,
                                  (r>>(4*j+2))&1 ? 1.f:0.f, (r>>(4*j+3))&1 ? 1.f:0.f));
    }
}

// ---------------- launch ----------------
extern "C" void kernel_launch(void* const* d_in, const int* in_sizes, int n_in,
                              void* d_out, int out_size){
    const float* sem   = (const float*)d_in[0];
    const float* depth = (const float*)d_in[1];
    const float* occ   = (const float*)d_in[2];
    const uint4* kept4 = (const uint4*)d_in[3];
    const float4* mapping = (const float4*)d_in[4];
    float* out = (float*)d_out;

    cudaFuncSetAttribute(k_small, cudaFuncAttributeMaxDynamicSharedMemorySize, SM2_BYTES);

    const int T = 256;
    const int WG = NWORDS/256;  // 512
    k_pix   <<<(BN*HW + T-1)/T, T>>>(sem, depth);
    k_small <<<BN, 512, SM2_BYTES>>>();
    k_feat  <<<dim3(30, 5, 30 + VZ), dim3(160, 2)>>>(occ, mapping, kept4, out);
    k_dpk   <<<WG, T>>>();
    k_unionw<<<WG, T>>>();
    k_dmask <<<WG, T>>>(out);
}

// round 16
// speedup vs baseline: 1.2110x; 1.0802x over previous
#include <cuda_runtime.h>
#include <math.h>

#define BN 2
#define KC 12
#define HH 120
#define WW 160
#define HW (HH*WW)          // 19200
#define NB 100
#define DD 128
#define NVOX (DD*DD*DD)
#define NVOXB (BN*NVOX)     // 4194304
#define NW 4                // 32-bit words per x-row
#define ROWW (NW*DD)        // word stride per z-slice = 512
#define NWORDS (NVOXB/32)   // 131072
#define NROWS (NWORDS/4)    // 32768 uint4 x-rows
#define WPB 65536           // words per batch
#define FEAT_ELEMS (BN*15*NB*HW)
#define FK_OFF FEAT_ELEMS
#define MASK_OFF (FEAT_ELEMS + NVOXB)

// voxel work appended to k_feat grid: z slices [30, 30+VZ); 4 voxels per thread
#define VZ 22               // 22*150 blocks * 320 thr * 4 vox = 4,224,000 >= NVOXB

// ---------------- scratch (device globals; no allocations) ----------------
__device__ float          g_sm[BN*KC*HW];   // softmax features
__device__ int            g_di[BN*HW];      // depth_index
__device__ unsigned char  g_sind[BN*HW];    // sem>=10 indicator
__device__ float          g_sd[BN*HW];      // clamped depth
__device__ float          g_sx[BN*WW];
__device__ float          g_sy[BN*HH];
__device__ uint4          g_pf4[NROWS];     // packed feat_kept (uint4 rows)
__device__ uint4          g_pk4[NROWS];     // packed kept
__device__ uint4          g_pa4[NROWS];     // packed padding_kept
__device__ uint4          g_pb4[NROWS];     // packed union
__device__ int            g_bp[BN];

// ---------------- stage 1: per-pixel softmax/argmax/depth (chip-wide) ----------------
__global__ void k_pix(const float* __restrict__ sem, const float* __restrict__ depth){
    int i = blockIdx.x*blockDim.x + threadIdx.x;
    if (i == 0){ g_bp[0] = 0; g_bp[1] = 0; }
    if (i >= BN*HW) return;
    int b = i / HW, p = i - b*HW;
    const float* s = sem + (size_t)b*KC*HW + p;
    float v[KC]; float mx = -1e30f; int am = 0;
    #pragma unroll
    for (int k = 0; k < KC; k++){ v[k] = s[(size_t)k*HW]; if (v[k] > mx){ mx = v[k]; am = k; } }
    float sum = 0.f;
    #pragma unroll
    for (int k = 0; k < KC; k++){ v[k] = expf(v[k]-mx); sum += v[k]; }
    float inv = 1.f/sum;
    float* o = g_sm + (size_t)b*KC*HW + p;
    #pragma unroll
    for (int k = 0; k < KC; k++) o[(size_t)k*HW] = v[k]*inv;
    g_sind[i] = (unsigned char)(am >= 10);
    float dc = fminf(depth[i], 6.f);
    g_di[i] = (int)(dc/6.f*100.f);
    g_sd[i] = dc;
}

// ---------------- stage 2: fused erosion + axis maxes + find_none (smem, 2 blocks) ----------------
__device__ void find_none_dev(const float* a, int n, float* out, float* suf){
    float run = INFINITY;
    for (int ii = n-1; ii >= 0; ii--){
        suf[ii] = run;
        float av = (a[ii] != 0.f) ? a[ii] : INFINITY;
        run = fminf(run, av);
    }
    float m = INFINITY;
    for (int ii = 0; ii < n; ii++){
        float l = isinf(m)      ? 0.f : m;
        float r = isinf(suf[ii])? 0.f : suf[ii];
        float val = (a[ii] == 0.f) ? fmaxf(l, r) : a[ii];
        if (val != 0.f) m = fminf(m, val);
        out[ii] = val;
    }
}

#define SM2_BYTES (HW*4 + HW + HW + (HH+WW+WW+HH)*4 + 16)

__global__ void k_small(){
    extern __shared__ unsigned char smraw[];
    float*         s_sd = (float*)smraw;
    unsigned char* s_si = (unsigned char*)(s_sd + HW);
    unsigned char* s_rm = s_si + HW;
    float* ymax = (float*)(s_rm + HW);
    float* xmax = ymax + HH;
    float* colm = xmax + WW;
    float* rowm = colm + WW;
    float* vv   = rowm + HH;

    int b = blockIdx.x, tid = threadIdx.x, nt = blockDim.x;
    int wid = tid >> 5, lane = tid & 31;

    for (int p = tid; p < HW; p += nt) s_si[p] = g_sind[b*HW + p];
    __syncthreads();
    for (int p = tid; p < HW; p += nt){
        int h = p / WW, w = p - h*WW;
        unsigned char m = 1;
        #pragma unroll
        for (int dw = -2; dw <= 2; dw++){
            int w2 = w + dw;
            if (w2 >= 0 && w2 < WW) m &= s_si[h*WW + w2];
        }
        s_rm[p] = m;
    }
    __syncthreads();
    for (int p = tid; p < HW; p += nt){
        int h = p / WW;
        unsigned char m = 1;
        #pragma unroll
        for (int dh = -2; dh <= 2; dh++){
            int h2 = h + dh;
            if (h2 >= 0 && h2 < HH) m &= s_rm[h2*WW + (p - h*WW)];
        }
        s_sd[p] = m ? g_sd[b*HW + p] : 0.f;
    }
    __syncthreads();

    // ymax: warp per row (lane-strided loads + shfl reduction)
    for (int h = wid; h < HH; h += 16){
        float m = 0.f;
        for (int w = lane; w < WW; w += 32) m = fmaxf(m, s_sd[h*WW + w]);
        #pragma unroll
        for (int off = 16; off > 0; off >>= 1) m = fmaxf(m, __shfl_xor_sync(0xffffffffu, m, off));
        if (lane == 0) ymax[h] = m;
    }
    // xmax: 3 h-chunks of 40, partials in scratch (s_si region, free now)
    {
        float* xpart = (float*)s_si;
        for (int i = tid; i < 3*WW; i += nt){
            int w = i % WW, c = i / WW;
            float m = 0.f;
            for (int h = c*40; h < c*40+40; h++) m = fmaxf(m, s_sd[h*WW + w]);
            xpart[i] = m;
        }
        __syncthreads();
        for (int w = tid; w < WW; w += nt)
            xmax[w] = fmaxf(xpart[w], fmaxf(xpart[WW+w], xpart[2*WW+w]));
    }
    __syncthreads();
    if (tid == 0){
        float a = 0.f; for (int h = 0; h < HH; h++)      if (ymax[h] != 0.f){ a = ymax[h]; break; } vv[0] = a;
        a = 0.f;       for (int h = HH-1; h >= 0; h--)   if (ymax[h] != 0.f){ a = ymax[h]; break; } vv[1] = a;
        a = 0.f;       for (int w = 0; w < WW; w++)      if (xmax[w] != 0.f){ a = xmax[w]; break; } vv[2] = a;
        a = 0.f;       for (int w = WW-1; w >= 0; w--)   if (xmax[w] != 0.f){ a = xmax[w]; break; } vv[3] = a;
    }
    __syncthreads();
    float vy = vv[0], vyr = vv[1], vx = vv[2], vxr = vv[3];
    auto sdval = [&](int h, int w) -> float {
        float v = s_sd[h*WW + w];
        if (w == 0)      return (v != 0.f) ? v : vx;
        if (w == WW-1)   return (v != 0.f) ? v : vxr;
        if (h == 0)      return (v != 0.f) ? v : vy;
        if (h == HH-1)   return (v != 0.f) ? v : vyr;
        return v;
    };
    // colm: chunked partials with sdval; rowm: warp per row with sdval
    {
        float* cpart = (float*)s_si;
        for (int i = tid; i < 3*WW; i += nt){
            int w = i % WW, c = i / WW;
            float m = 0.f;
            for (int h = c*40; h < c*40+40; h++) m = fmaxf(m, sdval(h, w));
            cpart[i] = m;
        }
        for (int h = wid; h < HH; h += 16){
            float m = 0.f;
            for (int w = lane; w < WW; w += 32) m = fmaxf(m, sdval(h, w));
            #pragma unroll
            for (int off = 16; off > 0; off >>= 1) m = fmaxf(m, __shfl_xor_sync(0xffffffffu, m, off));
            if (lane == 0) rowm[h] = m;
        }
        __syncthreads();
        for (int w = tid; w < WW; w += nt)
            colm[w] = fmaxf(cpart[w], fmaxf(cpart[WW+w], cpart[2*WW+w]));
    }
    __syncthreads();
    // find_none with smem suffix scratch (s_rm region, free now)
    float* suf0 = (float*)s_rm;
    float* suf1 = suf0 + WW;
    if (tid == 0)  find_none_dev(colm, WW, g_sx + b*WW, suf0);
    if (tid == 32) find_none_dev(rowm, HH, g_sy + b*HH, suf1);
}

// ---------------- stage 3: fused features + voxel gather (x4 vectorized) ----------------
__global__ void __launch_bounds__(320, 6)
k_feat(const float* __restrict__ occ,
       const float4* __restrict__ mapping,
       const uint4* __restrict__ kept4,
       float* __restrict__ out){
    if (blockIdx.z >= 30){
        // ---- voxel path: 4 voxels per thread ----
        int lb  = (blockIdx.z - 30)*150 + blockIdx.y*30 + blockIdx.x;
        int tid = threadIdx.y*160 + threadIdx.x;
        int q   = lb*320 + tid;                 // quad index
        if (q >= NVOXB/4) return;               // boundary retires whole warps
        uint4 kw = __ldcs(&kept4[q]);
        unsigned fnib = 0, knib = 0;
        float f[4];
        #pragma unroll
        for (int k = 0; k < 4; k++){
            unsigned kv = (&kw.x)[k];
            bool fk = false;
            if (kv){
                float4 m = __ldcs(&mapping[q*4 + k]);
                int b = (int)m.x, x = (int)m.y, y = (int)m.z;
                int didx = (int)(m.w*100.f/6.f);
                int di  = g_di[b*HW + y*WW + x];
                int dmb = (int)(fminf(g_sx[b*WW + x], g_sy[b*HH + y])/6.f*100.f);
                fk = (didx > di - 3) && (didx < dmb + 5);
            }
            f[k] = fk ? 1.f : 0.f;
            fnib |= (fk ? 1u : 0u) << k;
            knib |= (kv ? 1u : 0u) << k;
        }
        unsigned sh = 4*(tid & 7);
        unsigned fw = fnib << sh, kwp = knib << sh;
        #pragma unroll
        for (int off = 1; off < 8; off <<= 1){
            fw  |= __shfl_xor_sync(0xffffffffu, fw,  off);
            kwp |= __shfl_xor_sync(0xffffffffu, kwp, off);
        }
        if ((tid & 7) == 0){
            ((unsigned*)g_pf4)[q >> 3] = fw;
            ((unsigned*)g_pk4)[q >> 3] = kwp;
        }
        __stcs(&((float4*)out)[FK_OFF/4 + q], make_float4(f[0], f[1], f[2], f[3]));
        return;
    }
    // ---- feature path ----
    int p4 = blockIdx.x*160 + threadIdx.x;           // 0..4799
    int d0 = blockIdx.y*20 + threadIdx.y*10;         // 0..90 step 10
    int cz = blockIdx.z; int b = cz/15, c = cz - b*15;
    float4* ob = (float4*)out + (size_t)cz*NB*(HW/4) + p4;
    if (c < KC){
        float4 o = ((const float4*)g_sm)[(size_t)(b*KC + c)*(HW/4) + p4];
        #pragma unroll
        for (int q = 0; q < 10; q++)
            __stcs(&ob[(size_t)(d0+q)*(HW/4)], o);
    } else if (c == 13){
        const int4 di4 = ((const int4*)g_di)[b*(HW/4) + p4];
        #pragma unroll
        for (int q = 0; q < 10; q++){
            int d = d0 + q;
            float4 o;
            o.x = (d > di4.x) ? 1.f : ((d < di4.x) ? -1.f : 0.f);
            o.y = (d > di4.y) ? 1.f : ((d < di4.y) ? -1.f : 0.f);
            o.z = (d > di4.z) ? 1.f : ((d < di4.z) ? -1.f : 0.f);
            o.w = (d > di4.w) ? 1.f : ((d < di4.w) ? -1.f : 0.f);
            __stcs(&ob[(size_t)d*(HW/4)], o);
        }
    } else if (c == 14){
        const int4 di4 = ((const int4*)g_di)[b*(HW/4) + p4];
        #pragma unroll
        for (int q = 0; q < 10; q++){
            int d = d0 + q;
            float4 o;
            o.x = fabsf((float)(d - di4.x)*0.06f);
            o.y = fabsf((float)(d - di4.y)*0.06f);
            o.z = fabsf((float)(d - di4.z)*0.06f);
            o.w = fabsf((float)(d - di4.w)*0.06f);
            __stcs(&ob[(size_t)d*(HW/4)], o);
        }
    } else { // c == 12 : depth_weight
        int h = p4/40, w0 = (p4 - h*40)*4;
        float sy = g_sy[b*HH + h];
        const int4 di4 = ((const int4*)g_di)[b*(HW/4) + p4];
        int di[4] = {di4.x, di4.y, di4.z, di4.w};
        int dmb[4];
        #pragma unroll
        for (int l = 0; l < 4; l++)
            dmb[l] = (int)(fminf(g_sx[b*WW + w0 + l], sy)/6.f*100.f);
        const float4* occ4 = (const float4*)occ + (size_t)b*NB*(HW/4) + p4;
        #pragma unroll
        for (int q = 0; q < 10; q++){
            int d = d0 + q;
            float4 ov = __ldcs(&occ4[(size_t)d*(HW/4)]);
            float ovv[4] = {ov.x, ov.y, ov.z, ov.w};
            float res[4];
            #pragma unroll
            for (int l = 0; l < 4; l++){
                bool kp = (d > di[l] - 3) && (d < dmb[l] + 5);
                res[l] = kp ? (1.f/(1.f + expf(-ovv[l]))) : 0.f;
            }
            __stcs(&ob[(size_t)d*(HW/4)], make_float4(res[0], res[1], res[2], res[3]));
        }
    }
}

// ---------------- uint4 row helpers ----------------
__device__ __forceinline__ unsigned xd1(unsigned w){
    return w | (w<<1) | (w<<2) | (w>>1) | (w>>2);
}

// full 5^3 dilation of a 128-bit x-row: 25 uint4 loads + in-register x-shift
__device__ __forceinline__ uint4 dil3d_row(const uint4* vol, int t, int y, int z){
    uint4 a = make_uint4(0,0,0,0);
    #pragma unroll
    for (int dz = -2; dz <= 2; dz++){
        int zz = z + dz; if (zz < 0 || zz >= DD) continue;
        #pragma unroll
        for (int dy = -2; dy <= 2; dy++){
            int yy = y + dy; if (yy < 0 || yy >= DD) continue;
            uint4 v = vol[t + dz*DD + dy];
            a.x |= v.x; a.y |= v.y; a.z |= v.z; a.w |= v.w;
        }
    }
    uint4 d;
    d.x = xd1(a.x) | (a.y<<31) | (a.y<<30);
    d.y = xd1(a.y) | (a.x>>31) | (a.x>>30) | (a.z<<31) | (a.z<<30);
    d.z = xd1(a.z) | (a.y>>31) | (a.y>>30) | (a.w<<31) | (a.w<<30);
    d.w = xd1(a.w) | (a.z>>31) | (a.z>>30);
    return d;
}

// padding_kept = dil3d(feat_kept) & kept; popcount -> g_bp; &= ~feat_kept
__global__ void k_dpk(){
    __shared__ int sc;
    int t = blockIdx.x*256 + threadIdx.x;    // x-row index, NROWS exact
    int y = t & (DD-1), z = (t >> 7) & (DD-1);
    if (threadIdx.x == 0) sc = 0;
    __syncthreads();
    uint4 d = dil3d_row(g_pf4, t, y, z);
    uint4 k = g_pk4[t];
    uint4 f = g_pf4[t];
    uint4 a = make_uint4(d.x & k.x, d.y & k.y, d.z & k.z, d.w & k.w);
    g_pa4[t] = make_uint4(a.x & ~f.x, a.y & ~f.y, a.z & ~f.z, a.w & ~f.w);
    int cnt = __popc(a.x) + __popc(a.y) + __popc(a.z) + __popc(a.w);
    #pragma unroll
    for (int off = 16; off > 0; off >>= 1) cnt += __shfl_down_sync(0xffffffffu, cnt, off);
    if ((threadIdx.x & 31) == 0 && cnt) atomicAdd(&sc, cnt);
    __syncthreads();
    if (threadIdx.x == 0 && sc) atomicAdd(&g_bp[blockIdx.x >> 6], sc);  // 64 blocks/batch
}

// materialize union = feat_kept | padding_even (virtual fix bit)
__global__ void k_unionw(){
    int t = blockIdx.x*256 + threadIdx.x;
    int y = t & (DD-1), z = (t >> 7) & (DD-1);
    int b = t >> 14;
    uint4 pe = make_uint4(0,0,0,0);
    if (!(y & 1) && !(z & 1)){
        int fixt = (g_bp[b] == 0) ? (b*(DD*DD) + 127*DD + 127) : -1;
        auto L4 = [&](int j) -> uint4 {
            uint4 v = g_pa4[j];
            if (j == fixt) v.w |= 0x80000000u;
            return v;
        };
        uint4 q0 = L4(t), q1 = L4(t+1), q2 = L4(t+DD), q3 = L4(t+DD+1);
        unsigned qx = q0.x|q1.x|q2.x|q3.x, qy = q0.y|q1.y|q2.y|q3.y;
        unsigned qz = q0.z|q1.z|q2.z|q3.z, qw = q0.w|q1.w|q2.w|q3.w;
        pe.x = (qx | (qx>>1)) & 0x55555555u;
        pe.y = (qy | (qy>>1)) & 0x55555555u;
        pe.z = (qz | (qz>>1)) & 0x55555555u;
        pe.w = (qw | (qw>>1)) & 0x55555555u;
    }
    uint4 f = g_pf4[t];
    g_pb4[t] = make_uint4(f.x|pe.x, f.y|pe.y, f.z|pe.z, f.w|pe.w);
}

// ---------------- word-level dilation for k_dmask (proven R12 form) ----------------
template <typename F>
__device__ __forceinline__ unsigned dil3d_f(F load, int i){
    int t = i >> 2;
    int y = t & (DD-1);
    int z = (t >> 7) & (DD-1);
    unsigned zy = 0;
    #pragma unroll
    for (int dz = -2; dz <= 2; dz++){
        int zz = z + dz; if (zz < 0 || zz >= DD) continue;
        #pragma unroll
        for (int dy = -2; dy <= 2; dy++){
            int yy = y + dy; if (yy < 0 || yy >= DD) continue;
            zy |= load(i + (dz*DD + dy)*NW);
        }
    }
    int wx = i & (NW-1);
    unsigned p = __shfl_up_sync(0xffffffffu, zy, 1);
    unsigned n = __shfl_down_sync(0xffffffffu, zy, 1);
    if (wx == 0)    p = 0u;
    if (wx == NW-1) n = 0u;
    return zy | (zy<<1) | (zy<<2) | (zy>>1) | (zy>>2)
              | (p>>31) | (p>>30) | (n<<31) | (n<<30);
}

// mask = dil3d(union), unpacked to floats
__global__ void k_dmask(float* __restrict__ out){
    int i = blockIdx.x*256 + threadIdx.x;
    const unsigned* pb = (const unsigned*)g_pb4;
    unsigned r = dil3d_f([&](int j){ return pb[j]; }, i);
    float4* o = (float4*)(out + MASK_OFF + (size_t)i*32);
    #pragma unroll
    for (int j = 0; j < 8; j++){
        __stcs(&o[j], make_float4((r>>(4*j))&1 ? 1.f:0.f, (r>>(4*j+1))&1 ? 1.f:0.f,
                                  (r>>(4*j+2))&1 ? 1.f:0.f, (r>>(4*j+3))&1 ? 1.f:0.f));
    }
}

// ---------------- launch ----------------
extern "C" void kernel_launch(void* const* d_in, const int* in_sizes, int n_in,
                              void* d_out, int out_size){
    const float* sem   = (const float*)d_in[0];
    const float* depth = (const float*)d_in[1];
    const float* occ   = (const float*)d_in[2];
    const uint4* kept4 = (const uint4*)d_in[3];
    const float4* mapping = (const float4*)d_in[4];
    float* out = (float*)d_out;

    cudaFuncSetAttribute(k_small, cudaFuncAttributeMaxDynamicSharedMemorySize, SM2_BYTES);

    const int T = 256;
    k_pix   <<<(BN*HW + T-1)/T, T>>>(sem, depth);
    k_small <<<BN, 512, SM2_BYTES>>>();
    k_feat  <<<dim3(30, 5, 30 + VZ), dim3(160, 2)>>>(occ, mapping, kept4, out);
    k_dpk   <<<NROWS/256, 256>>>();
    k_unionw<<<NROWS/256, 256>>>();
    k_dmask <<<NWORDS/256, 256>>>(out);
}